// round 13
// baseline (speedup 1.0000x reference)
#include <cuda_runtime.h>

#define NQ    12
#define NBITS 12
#define DIM   4096
#define TV    4          // vectors (rows or cols) per block
#define VSZ   4100       // padded vector stride in float2 units
#define NTHR  512

// Intermediate Y = X @ U^H (complex), static scratch (sanctioned workaround)
__device__ float2 g_Y[(size_t)DIM * DIM];

__device__ __forceinline__ float2 cmul(float2 a, float2 b) {
    return make_float2(a.x * b.x - a.y * b.y, a.x * b.y + a.y * b.x);
}

// a*x + b*y (complex), 8 FFMA-class ops
__device__ __forceinline__ float2 cfma2(float2 a, float2 x, float2 b, float2 y) {
    float re = fmaf(a.x, x.x, fmaf(-a.y, x.y, fmaf(b.x, y.x, -b.y * y.y)));
    float im = fmaf(a.x, x.y, fmaf(a.y, x.x, fmaf(b.x, y.y,  b.y * y.x)));
    return make_float2(re, im);
}

// 12 fused gates uq = rz@ry@rx; sgn=-1 conjugates (row pass applies conj(U)).
__device__ __forceinline__ void make_gates(const float* __restrict__ w,
                                           float2 (*sg)[4], int tid, float sgn) {
    if (tid < NQ) {
        const int q = tid;
        const float WM = 0.632455532033675866f;   // sqrt(2/5)
        float hx = 0.5f * (w[3 * q + 0] * WM);
        float hy = 0.5f * (w[3 * q + 1] * WM);
        float hz = 0.5f * (w[3 * q + 2] * WM);
        float cx = cosf(hx), sx = sinf(hx);
        float cy = cosf(hy), sy = sinf(hy);
        float cz = cosf(hz), sz = sinf(hz);
        float2 m00 = make_float2( cy * cx,  sy * sx);
        float2 m01 = make_float2(-sy * cx, -cy * sx);
        float2 m10 = make_float2( sy * cx, -cy * sx);
        float2 m11 = make_float2( cy * cx, -sy * sx);
        float2 e  = make_float2(cz, -sz);           // exp(-i*hz)
        float2 ec = make_float2(cz,  sz);
        float2 u0 = cmul(e,  m00), u1 = cmul(e,  m01);
        float2 u2 = cmul(ec, m10), u3 = cmul(ec, m11);
        u0.y *= sgn; u1.y *= sgn; u2.y *= sgn; u3.y *= sgn;
        sg[q][0] = u0; sg[q][1] = u1; sg[q][2] = u2; sg[q][3] = u3;
    }
}

// Shared butterfly core: 6 radix-4 stages over the TV vectors in SMEM.
__device__ __forceinline__ void butterfly_smem(float2* s, const float2 (*sg)[4], int tid) {
    for (int bl = 0; bl < NBITS; bl += 2) {
        float2 A00 = sg[NBITS - 1 - bl][0], A01 = sg[NBITS - 1 - bl][1];
        float2 A10 = sg[NBITS - 1 - bl][2], A11 = sg[NBITS - 1 - bl][3];
        float2 B00 = sg[NBITS - 2 - bl][0], B01 = sg[NBITS - 2 - bl][1];
        float2 B10 = sg[NBITS - 2 - bl][2], B11 = sg[NBITS - 2 - bl][3];
        const int sL = 1 << bl;
        for (int g = tid; g < TV * (DIM / 4); g += NTHR) {
            int v = g >> (NBITS - 2);
            int r = g & (DIM / 4 - 1);
            float2* p = s + v * VSZ;
            int base = ((r >> bl) << (bl + 2)) | (r & (sL - 1));
            int i0 = base, i1 = base + sL, i2 = base + 2 * sL, i3 = base + 3 * sL;
            float2 e0 = p[i0], e1 = p[i1], e2 = p[i2], e3 = p[i3];
            float2 t0 = cfma2(A00, e0, A01, e1);
            float2 t1 = cfma2(A10, e0, A11, e1);
            float2 t2 = cfma2(A00, e2, A01, e3);
            float2 t3 = cfma2(A10, e2, A11, e3);
            p[i0] = cfma2(B00, t0, B01, t2);
            p[i2] = cfma2(B10, t0, B11, t2);
            p[i1] = cfma2(B00, t1, B01, t3);
            p[i3] = cfma2(B10, t1, B11, t3);
        }
        __syncthreads();
    }
}

// Pass A: g_Y[r,:] = conj(U) @ X[r,:]   (rows of real X)
__global__ void __launch_bounds__(NTHR, 1)
pqc_rows_kernel(const float* __restrict__ X, const float* __restrict__ w) {
    extern __shared__ float2 s[];
    __shared__ float2 sg[NQ][4];
    const int tid = threadIdx.x;
    const int r0 = blockIdx.x * TV;
    make_gates(w, sg, tid, -1.f);

    for (int n = tid; n < TV * DIM; n += NTHR) {
        int v = n >> NBITS;
        int c = n & (DIM - 1);
        s[v * VSZ + c] = make_float2(X[(size_t)(r0 + v) * DIM + c], 0.f);
    }
    __syncthreads();

    butterfly_smem(s, sg, tid);

    for (int n = tid; n < TV * DIM; n += NTHR) {
        int v = n >> NBITS;
        int c = n & (DIM - 1);
        g_Y[(size_t)(r0 + v) * DIM + c] = s[v * VSZ + c];
    }
}

// Pass B: Z[:,c] = U @ g_Y[:,c]  (columns); store adapted to out dtype/size.
__global__ void __launch_bounds__(NTHR, 1)
pqc_cols_kernel(float* __restrict__ out, int out_n, const float* __restrict__ w) {
    extern __shared__ float2 s[];
    __shared__ float2 sg[NQ][4];
    const int tid = threadIdx.x;
    const int c0 = blockIdx.x * TV;
    make_gates(w, sg, tid, 1.f);

    for (int n = tid; n < TV * DIM; n += NTHR) {
        int row = n >> 2;                    // TV == 4
        int v   = n & 3;
        s[v * VSZ + row] = g_Y[(size_t)row * DIM + c0 + v];
    }
    __syncthreads();

    butterfly_smem(s, sg, tid);

    const bool interleaved = (out_n >= 2 * DIM * DIM);
    for (int n = tid; n < TV * DIM; n += NTHR) {
        int row = n >> 2;
        int v   = n & 3;
        float2 val = s[v * VSZ + row];
        size_t idx = (size_t)row * DIM + c0 + v;
        if (interleaved) {
            size_t fo = 2 * idx;
            if (fo + 1 < (size_t)out_n) { out[fo] = val.x; out[fo + 1] = val.y; }
        } else {
            if (idx < (size_t)out_n) out[idx] = val.x;   // real part only
        }
    }
}

extern "C" void kernel_launch(void* const* d_in, const int* in_sizes, int n_in,
                              void* d_out, int out_size) {
    if (n_in < 2) return;
    const float* w = (const float*)d_in[0];
    const float* x = (const float*)d_in[1];
    if (in_sizes[0] > in_sizes[1]) {   // defensive: weight is the 36-elem input
        const float* t = w; w = x; x = t;
    }

    const int smem = TV * VSZ * (int)sizeof(float2);   // 131200 B dynamic
    cudaFuncSetAttribute(pqc_rows_kernel,
                         cudaFuncAttributeMaxDynamicSharedMemorySize, smem);
    cudaFuncSetAttribute(pqc_cols_kernel,
                         cudaFuncAttributeMaxDynamicSharedMemorySize, smem);

    pqc_rows_kernel<<<DIM / TV, NTHR, smem>>>(x, w);
    pqc_cols_kernel<<<DIM / TV, NTHR, smem>>>((float*)d_out, out_size, w);
}

// round 14
// speedup vs baseline: 1.6108x; 1.6108x over previous
#include <cuda_runtime.h>

#define NQ    12
#define NBITS 12
#define DIM   4096
#define NTHR  256

// Intermediate Y = X @ U^H (complex), static scratch (sanctioned workaround)
__device__ float2 g_Y[(size_t)DIM * DIM];

__device__ __forceinline__ float2 cmul(float2 a, float2 b) {
    return make_float2(a.x * b.x - a.y * b.y, a.x * b.y + a.y * b.x);
}

// a*x + b*y (complex), 8 FFMA-class ops
__device__ __forceinline__ float2 cfma2(float2 a, float2 x, float2 b, float2 y) {
    float re = fmaf(a.x, x.x, fmaf(-a.y, x.y, fmaf(b.x, y.x, -b.y * y.y)));
    float im = fmaf(a.x, x.y, fmaf(a.y, x.x, fmaf(b.x, y.y,  b.y * y.x)));
    return make_float2(re, im);
}

// 12 fused gates uq = rz@ry@rx; sgn=-1 conjugates (row pass applies conj(U)).
__device__ __forceinline__ void make_gates(const float* __restrict__ w,
                                           float2 (*sg)[4], int tid, float sgn) {
    if (tid < NQ) {
        const int q = tid;
        const float WM = 0.632455532033675866f;   // sqrt(2/5)
        float hx = 0.5f * (w[3 * q + 0] * WM);
        float hy = 0.5f * (w[3 * q + 1] * WM);
        float hz = 0.5f * (w[3 * q + 2] * WM);
        float cx = cosf(hx), sx = sinf(hx);
        float cy = cosf(hy), sy = sinf(hy);
        float cz = cosf(hz), sz = sinf(hz);
        float2 m00 = make_float2( cy * cx,  sy * sx);
        float2 m01 = make_float2(-sy * cx, -cy * sx);
        float2 m10 = make_float2( sy * cx, -cy * sx);
        float2 m11 = make_float2( cy * cx, -sy * sx);
        float2 e  = make_float2(cz, -sz);           // exp(-i*hz)
        float2 ec = make_float2(cz,  sz);
        float2 u0 = cmul(e,  m00), u1 = cmul(e,  m01);
        float2 u2 = cmul(ec, m10), u3 = cmul(ec, m11);
        u0.y *= sgn; u1.y *= sgn; u2.y *= sgn; u3.y *= sgn;
        sg[q][0] = u0; sg[q][1] = u1; sg[q][2] = u2; sg[q][3] = u3;
    }
}

// Apply 4 gate sub-stages (index bits bl..bl+3) to 16 register elements.
__device__ __forceinline__ void butterfly16(float2 v[16], const float2 (*sg)[4], int bl) {
#pragma unroll
    for (int k = 0; k < 4; k++) {
        const float2* G = sg[NBITS - 1 - (bl + k)];
        float2 G00 = G[0], G01 = G[1], G10 = G[2], G11 = G[3];
#pragma unroll
        for (int e = 0; e < 16; e++) {
            if (e & (1 << k)) continue;
            int e1 = e | (1 << k);
            float2 a = v[e], b = v[e1];
            v[e]  = cfma2(G00, a, G01, b);
            v[e1] = cfma2(G10, a, G11, b);
        }
    }
}

// Bank swizzle on float2 index: XOR bits [1:4) with bits [4:7).
__device__ __forceinline__ int swz(int c) { return c ^ (((c >> 4) & 7) << 1); }

// K1 — row pass: g_Y[r,:] = conj(U) @ X[r,:]. One row per block.
__global__ void __launch_bounds__(NTHR)
k_rows(const float* __restrict__ X, const float* __restrict__ w) {
    __shared__ float2 sg[NQ][4];
    __shared__ float2 s[DIM];                       // 32 KB
    const int tid = threadIdx.x;
    make_gates(w, sg, tid, -1.f);
    __syncthreads();

    const int r = blockIdx.x;
    float2 v[16];

    // stage 1: bits 0-3, contiguous 16 elements from global (real input)
    {
        const float4* xp = (const float4*)(X + (size_t)r * DIM) + tid * 4;
#pragma unroll
        for (int i = 0; i < 4; i++) {
            float4 a = xp[i];
            v[4 * i + 0] = make_float2(a.x, 0.f);
            v[4 * i + 1] = make_float2(a.y, 0.f);
            v[4 * i + 2] = make_float2(a.z, 0.f);
            v[4 * i + 3] = make_float2(a.w, 0.f);
        }
        butterfly16(v, sg, 0);
        // store pairs as float4 at swizzled pair index (conflict-free)
        float4* s4 = (float4*)s;
#pragma unroll
        for (int m = 0; m < 8; m++)
            s4[(8 * tid + m) ^ (tid & 7)] =
                make_float4(v[2 * m].x, v[2 * m].y, v[2 * m + 1].x, v[2 * m + 1].y);
    }
    __syncthreads();

    // stage 2: bits 4-7 (stride 16)
    {
        const int clow = tid & 15, chi = tid >> 4;
#pragma unroll
        for (int e = 0; e < 16; e++)
            v[e] = s[swz(clow | (e << 4) | (chi << 8))];
        butterfly16(v, sg, 4);
#pragma unroll
        for (int e = 0; e < 16; e++)
            s[swz(clow | (e << 4) | (chi << 8))] = v[e];
    }
    __syncthreads();

    // stage 3: bits 8-11 (stride 256), then coalesced store to g_Y
    {
#pragma unroll
        for (int e = 0; e < 16; e++)
            v[e] = s[swz(tid | (e << 8))];
        butterfly16(v, sg, 8);
        float2* yp = g_Y + (size_t)r * DIM;
#pragma unroll
        for (int e = 0; e < 16; e++)
            yp[tid | (e << 8)] = v[e];
    }
}

// Shared 64-row tile butterfly: 3 radix-4 stages over local row bits 0..5.
// qb = qubit index of local row bit 0. Lanes run along columns: conflict-free.
__device__ __forceinline__ void tile_butterfly(float2* s, const float2 (*sg)[4],
                                               int tid, int qb) {
#pragma unroll
    for (int bl = 0; bl < 6; bl += 2) {
        float2 A00 = sg[qb - bl][0],     A01 = sg[qb - bl][1];
        float2 A10 = sg[qb - bl][2],     A11 = sg[qb - bl][3];
        float2 B00 = sg[qb - bl - 1][0], B01 = sg[qb - bl - 1][1];
        float2 B10 = sg[qb - bl - 1][2], B11 = sg[qb - bl - 1][3];
        const int sL = 1 << bl;
#pragma unroll
        for (int n = tid; n < 1024; n += NTHR) {    // 16 row-groups x 64 cols
            int c = n & 63, q = n >> 6;
            int base = ((q >> bl) << (bl + 2)) | (q & (sL - 1));
            float2* p = s + c;
            int i0 = base * 65, i1 = (base + sL) * 65,
                i2 = (base + 2 * sL) * 65, i3 = (base + 3 * sL) * 65;
            float2 e0 = p[i0], e1 = p[i1], e2 = p[i2], e3 = p[i3];
            float2 t0 = cfma2(A00, e0, A01, e1);
            float2 t1 = cfma2(A10, e0, A11, e1);
            float2 t2 = cfma2(A00, e2, A01, e3);
            float2 t3 = cfma2(A10, e2, A11, e3);
            p[i0] = cfma2(B00, t0, B01, t2);
            p[i2] = cfma2(B10, t0, B11, t2);
            p[i1] = cfma2(B00, t1, B01, t3);
            p[i3] = cfma2(B10, t1, B11, t3);
        }
        __syncthreads();
    }
}

// K2 — column pass, row bits 0-5 (qubits 11..6). Tile: 64 rows x 64 cols.
__global__ void __launch_bounds__(NTHR)
k_cols_lo(const float* __restrict__ w) {
    __shared__ float2 sg[NQ][4];
    __shared__ float2 s[64 * 65];                   // 33.3 KB, padded stride
    const int tid = threadIdx.x;
    make_gates(w, sg, tid, 1.f);
    __syncthreads();

    const int r0 = blockIdx.y * 64, c0 = blockIdx.x * 64;
#pragma unroll
    for (int n = tid; n < 4096; n += NTHR) {
        int i = n >> 6, c = n & 63;
        s[i * 65 + c] = g_Y[(size_t)(r0 + i) * DIM + c0 + c];
    }
    __syncthreads();

    tile_butterfly(s, sg, tid, 11);                 // local row bit 0 -> qubit 11

#pragma unroll
    for (int n = tid; n < 4096; n += NTHR) {
        int i = n >> 6, c = n & 63;
        g_Y[(size_t)(r0 + i) * DIM + c0 + c] = s[i * 65 + c];
    }
}

// K3 — column pass, row bits 6-11 (qubits 5..0). Rows r_lo + 64k, k=0..63.
// Writes the final output (dtype-adaptive, guarded).
__global__ void __launch_bounds__(NTHR)
k_cols_hi(float* __restrict__ out, int out_n, const float* __restrict__ w) {
    __shared__ float2 sg[NQ][4];
    __shared__ float2 s[64 * 65];
    const int tid = threadIdx.x;
    make_gates(w, sg, tid, 1.f);
    __syncthreads();

    const int rlo = blockIdx.y, c0 = blockIdx.x * 64;
#pragma unroll
    for (int n = tid; n < 4096; n += NTHR) {
        int k = n >> 6, c = n & 63;
        s[k * 65 + c] = g_Y[(size_t)(rlo + (k << 6)) * DIM + c0 + c];
    }
    __syncthreads();

    tile_butterfly(s, sg, tid, 5);                  // local row bit 0 -> qubit 5

    const bool interleaved = (out_n >= 2 * DIM * DIM);
#pragma unroll
    for (int n = tid; n < 4096; n += NTHR) {
        int k = n >> 6, c = n & 63;
        float2 val = s[k * 65 + c];
        size_t idx = (size_t)(rlo + (k << 6)) * DIM + c0 + c;
        if (interleaved) {
            size_t fo = 2 * idx;
            if (fo + 1 < (size_t)out_n) { out[fo] = val.x; out[fo + 1] = val.y; }
        } else {
            if (idx < (size_t)out_n) out[idx] = val.x;
        }
    }
}

extern "C" void kernel_launch(void* const* d_in, const int* in_sizes, int n_in,
                              void* d_out, int out_size) {
    if (n_in < 2) return;
    const float* w = (const float*)d_in[0];
    const float* x = (const float*)d_in[1];
    if (in_sizes[0] > in_sizes[1]) {   // defensive: weight is the 36-elem input
        const float* t = w; w = x; x = t;
    }

    k_rows<<<DIM, NTHR>>>(x, w);                          // Y = X @ U^H (rows)
    dim3 tg(DIM / 64, DIM / 64);
    k_cols_lo<<<tg, NTHR>>>(w);                           // U on row bits 0-5
    k_cols_hi<<<tg, NTHR>>>((float*)d_out, out_size, w);  // U on row bits 6-11 -> out
}